// round 2
// baseline (speedup 1.0000x reference)
#include <cuda_runtime.h>
#include <cstdint>

// Problem constants (from reference)
#define NUM_VERTS 6890
#define NUM_FACES 13776
#define H_DIM 1024
#define W_DIM 1024
#define HW (H_DIM * W_DIM)
#define NBATCH 16

// Exploits:
//  1. Reference gathers only batch-0 faces/verts and broadcasts the (H,W,3)
//     result across all 16 batches -> compute each pixel once, write 16x.
//  2. JAX default config disables x64, so the "int64" index tensors are
//     actually int32 on device -> read as int.

__global__ __launch_bounds__(256) void uv_render_kernel(
    const float* __restrict__ verts,   // (16, 6890, 3) fp32 — only batch 0 used
    const int*   __restrict__ faces,   // (13776, 3) int32
    const int*   __restrict__ pix,     // (1024, 1024) int32
    const float* __restrict__ bary,    // (1024, 1024, 3) fp32
    float* __restrict__ out)           // (16, 1024, 1024, 3) fp32
{
    const int t = blockIdx.x * blockDim.x + threadIdx.x;
    const int p0 = t * 4;              // 4 pixels per thread
    if (p0 >= HW) return;

    // --- 4 pixel ids: one int4 (16B, aligned) ---
    const int4 pi = *reinterpret_cast<const int4*>(pix + p0);
    int pf[4] = { pi.x, pi.y, pi.z, pi.w };

    // --- 12 bary coords: 3x float4 (48B, 16B-aligned since p0*3*4 = t*48) ---
    const float4* b4 = reinterpret_cast<const float4*>(bary + (size_t)p0 * 3);
    float4 bA = b4[0], bB = b4[1], bC = b4[2];
    float bar[12] = { bA.x, bA.y, bA.z, bA.w,
                      bB.x, bB.y, bB.z, bB.w,
                      bC.x, bC.y, bC.z, bC.w };

    float res[12];
#pragma unroll
    for (int i = 0; i < 4; i++) {
        int f = pf[i];
        float a0 = 0.f, a1 = 0.f, a2 = 0.f;
        if (f >= 0) {
            if (f >= NUM_FACES) f = 0;            // safety clamp (no-op if dtype right)
            // faces table (~165KB) and batch-0 verts (~82KB) are L1/L2 hot
#pragma unroll
            for (int k = 0; k < 3; k++) {
                int vi = faces[f * 3 + k];
                if (vi < 0 || vi >= NUM_VERTS) vi = 0;  // safety clamp
                const float* vp = verts + (size_t)vi * 3;
                float w = bar[i * 3 + k];
                a0 += w * vp[0];
                a1 += w * vp[1];
                a2 += w * vp[2];
            }
        }
        res[i * 3 + 0] = a0;
        res[i * 3 + 1] = a1;
        res[i * 3 + 2] = a2;
    }

    float4 o0 = make_float4(res[0], res[1], res[2],  res[3]);
    float4 o1 = make_float4(res[4], res[5], res[6],  res[7]);
    float4 o2 = make_float4(res[8], res[9], res[10], res[11]);

    // --- write the same 48B to all 16 batch slices (coalesced, 16B aligned) ---
    const size_t base = (size_t)p0 * 3;
    const size_t bstride = (size_t)HW * 3;   // 12 MB / batch in floats
#pragma unroll
    for (int n = 0; n < NBATCH; n++) {
        float4* op = reinterpret_cast<float4*>(out + base + (size_t)n * bstride);
        op[0] = o0;
        op[1] = o1;
        op[2] = o2;
    }
}

extern "C" void kernel_launch(void* const* d_in, const int* in_sizes, int n_in,
                              void* d_out, int out_size)
{
    const float* verts = (const float*)d_in[0];   // verts_attr (16,6890,3) f32
    const int*   faces = (const int*)d_in[1];     // face_tensor (13776,3) i32
    const int*   pix   = (const int*)d_in[2];     // pix_to_face (1024,1024) i32
    const float* bary  = (const float*)d_in[3];   // bary_coords (1024,1024,3) f32
    float* out = (float*)d_out;                   // (16,1024,1024,3) f32

    const int threads = 256;
    const int total_threads = HW / 4;             // 262144 threads, 4 px each
    const int blocks = total_threads / threads;   // 1024
    uv_render_kernel<<<blocks, threads>>>(verts, faces, pix, bary, out);
}

// round 3
// speedup vs baseline: 1.5380x; 1.5380x over previous
#include <cuda_runtime.h>
#include <cstdint>

// Problem constants
#define NUM_VERTS 6890
#define NUM_FACES 13776
#define HW (1024 * 1024)
#define NBATCH 16
#define THREADS 256
#define PX_PER_THREAD 4
#define PX_PER_BLOCK (THREADS * PX_PER_THREAD)      // 1024 pixels
#define TILE_FLOATS (PX_PER_BLOCK * 3)              // 3072 floats
#define TILE_BYTES (TILE_FLOATS * 4)                // 12288 B per batch-tile

// Exploits:
//  1. Reference gathers only batch-0 faces/verts and broadcasts the (H,W,3)
//     map across all 16 batches -> compute once, replicate 16x.
//  2. JAX x64 disabled -> "int64" index tensors are int32 on device.
//  3. TMA bulk stores (cp.async.bulk) do the 16x replication from smem,
//     removing 48 STG.128 per thread (R2 ncu: L1=67.5% was the binding unit).

__global__ __launch_bounds__(THREADS) void uv_render_kernel(
    const float* __restrict__ verts,   // (16, 6890, 3) fp32 — only batch 0 used
    const int*   __restrict__ faces,   // (13776, 3) int32
    const int*   __restrict__ pix,     // (1024, 1024) int32
    const float* __restrict__ bary,    // (1024, 1024, 3) fp32
    float* __restrict__ out)           // (16, 1024, 1024, 3) fp32
{
    __shared__ __align__(128) float tile[TILE_FLOATS];   // 12 KB

    const int t  = blockIdx.x * blockDim.x + threadIdx.x;
    const int p0 = t * PX_PER_THREAD;

    // ---- 4 pixel ids: one int4 (aligned) ----
    const int4 pi = *reinterpret_cast<const int4*>(pix + p0);
    int pf[4] = { pi.x, pi.y, pi.z, pi.w };

    // ---- 12 bary coords: 3x float4 (48B, aligned) ----
    const float4* b4 = reinterpret_cast<const float4*>(bary + (size_t)p0 * 3);
    float4 bA = b4[0], bB = b4[1], bC = b4[2];
    const float bar[12] = { bA.x, bA.y, bA.z, bA.w,
                            bB.x, bB.y, bB.z, bB.w,
                            bC.x, bC.y, bC.z, bC.w };

    // ---- phase 1: all 12 face-vertex indices in flight together ----
    int vid[4][3];
#pragma unroll
    for (int i = 0; i < 4; i++) {
        int f = pf[i];
        f = (f < 0 || f >= NUM_FACES) ? 0 : f;   // bg -> gather face 0, mask later
        const int* fr = faces + f * 3;
#pragma unroll
        for (int k = 0; k < 3; k++) vid[i][k] = fr[k];
    }

    // ---- phase 2: all 36 vertex components in flight together ----
    float va[4][3][3];
#pragma unroll
    for (int i = 0; i < 4; i++) {
#pragma unroll
        for (int k = 0; k < 3; k++) {
            int vi = vid[i][k];
            vi = (vi < 0 || vi >= NUM_VERTS) ? 0 : vi;
            const float* vp = verts + vi * 3;
            va[i][k][0] = vp[0];
            va[i][k][1] = vp[1];
            va[i][k][2] = vp[2];
        }
    }

    // ---- phase 3: weighted sum, mask background ----
    float res[12];
#pragma unroll
    for (int i = 0; i < 4; i++) {
        const float m = (pf[i] >= 0) ? 1.0f : 0.0f;
#pragma unroll
        for (int d = 0; d < 3; d++) {
            float a = bar[i * 3 + 0] * va[i][0][d]
                    + bar[i * 3 + 1] * va[i][1][d]
                    + bar[i * 3 + 2] * va[i][2][d];
            res[i * 3 + d] = a * m;
        }
    }

    // ---- store tile to smem (3x STS.128, conflict-free linear) ----
    {
        float4* t4 = reinterpret_cast<float4*>(tile) + threadIdx.x * 3;
        t4[0] = make_float4(res[0], res[1], res[2],  res[3]);
        t4[1] = make_float4(res[4], res[5], res[6],  res[7]);
        t4[2] = make_float4(res[8], res[9], res[10], res[11]);
    }
    __syncthreads();

    // ---- one thread TMA-bulk-stores the tile to all 16 batch slices ----
    if (threadIdx.x == 0) {
        asm volatile("fence.proxy.async.shared::cta;" ::: "memory");
        uint32_t saddr;
        asm("{ .reg .u64 tmp; cvta.to.shared.u64 tmp, %1; cvt.u32.u64 %0, tmp; }"
            : "=r"(saddr) : "l"(tile));
        const size_t gbase   = (size_t)blockIdx.x * TILE_FLOATS;
        const size_t bstride = (size_t)HW * 3;
#pragma unroll
        for (int n = 0; n < NBATCH; n++) {
            float* dst = out + gbase + (size_t)n * bstride;
            asm volatile(
                "cp.async.bulk.global.shared::cta.bulk_group [%0], [%1], %2;"
                :: "l"(dst), "r"(saddr), "n"(TILE_BYTES) : "memory");
        }
        asm volatile("cp.async.bulk.commit_group;" ::: "memory");
        asm volatile("cp.async.bulk.wait_group 0;" ::: "memory");
    }
}

extern "C" void kernel_launch(void* const* d_in, const int* in_sizes, int n_in,
                              void* d_out, int out_size)
{
    const float* verts = (const float*)d_in[0];
    const int*   faces = (const int*)d_in[1];
    const int*   pix   = (const int*)d_in[2];
    const float* bary  = (const float*)d_in[3];
    float* out = (float*)d_out;

    const int blocks = HW / PX_PER_BLOCK;   // 1024
    uv_render_kernel<<<blocks, THREADS>>>(verts, faces, pix, bary, out);
}